// round 10
// baseline (speedup 1.0000x reference)
#include <cuda_runtime.h>

// cvx_knapsack_solver: batched PGD + knapsack projection (warm-started 2-eval
// within-projection secant on the piecewise-linear g, bracket-clamped [0,2]).
// Layout: 8 lanes/row, 8 items/lane, ONE row per thread -> 4096 warps for
// latency hiding. Full 3-SHFL xor-tree gives every lane the reduced value, so
// the scalar secant chain runs uniformly with no broadcasts.

#define BROWS   16384
#define NITEMS  64
#define TPR     8
#define IPT     8
#define NPAIR   4          // IPT/2 float2 pairs
#define CAPC    102.0f
#define NPGD    120
#define ETAC    0.1f
#define NIT0    8          // secant evals, cold first projection
#define NIT     2          // secant evals, warm-started projections
#define HI0     2.0f       // g(HI0)=0 guaranteed: y <= ~1.6, w >= 1

// Packed dual-fp32 FMA (Blackwell FFMA2). mov.b64 is register pairing only.
__device__ __forceinline__ float2 fma2(float2 a, float2 b, float2 c) {
    float2 r;
    asm("{\n\t"
        ".reg .b64 ra, rb, rc, rd;\n\t"
        "mov.b64 ra, {%2, %3};\n\t"
        "mov.b64 rb, {%4, %5};\n\t"
        "mov.b64 rc, {%6, %7};\n\t"
        "fma.rn.f32x2 rd, ra, rb, rc;\n\t"
        "mov.b64 {%0, %1}, rd;\n\t"
        "}"
        : "=f"(r.x), "=f"(r.y)
        : "f"(a.x), "f"(a.y), "f"(b.x), "f"(b.y), "f"(c.x), "f"(c.y));
    return r;
}

__device__ __forceinline__ float2 clip01(float2 z) {
    z.x = fminf(fmaxf(z.x, 0.f), 1.f);
    z.y = fminf(fmaxf(z.y, 0.f), 1.f);
    return z;
}

// Sum over the row's 8-lane group; result valid in ALL 8 lanes.
__device__ __forceinline__ float red8(float v) {
    v += __shfl_xor_sync(0xffffffffu, v, 1);
    v += __shfl_xor_sync(0xffffffffu, v, 2);
    v += __shfl_xor_sync(0xffffffffu, v, 4);
    return v;
}

// f = g(lam) - CAP, reduced over the row's 8 lanes (uniform in all lanes).
__device__ __forceinline__ float evalg(const float2 x[NPAIR],
                                       const float2 w[NPAIR], float lam) {
    float2 m = make_float2(-lam, -lam);
    float2 sa = make_float2(0.f, 0.f);
    float2 sb = make_float2(0.f, 0.f);
#pragma unroll
    for (int j = 0; j < NPAIR; j += 2) {
        float2 z0 = clip01(fma2(m, w[j],     x[j]));
        float2 z1 = clip01(fma2(m, w[j + 1], x[j + 1]));
        sa = fma2(z0, w[j],     sa);
        sb = fma2(z1, w[j + 1], sb);
    }
    float2 s = make_float2(sa.x + sb.x, sa.y + sb.y);
    return red8(s.x + s.y) - CAPC;
}

// x = clip(x - lam*w, 0, 1); return this lane's ||x||^2 partial.
__device__ __forceinline__ float applyp(float2 x[NPAIR],
                                        const float2 w[NPAIR], float lam) {
    float2 m = make_float2(-lam, -lam);
    float2 aa = make_float2(0.f, 0.f);
    float2 ab = make_float2(0.f, 0.f);
#pragma unroll
    for (int j = 0; j < NPAIR; j += 2) {
        x[j]     = clip01(fma2(m, w[j],     x[j]));
        x[j + 1] = clip01(fma2(m, w[j + 1], x[j + 1]));
        aa = fma2(x[j],     x[j],     aa);
        ab = fma2(x[j + 1], x[j + 1], ab);
    }
    return aa.x + aa.y + ab.x + ab.y;
}

__global__ void __launch_bounds__(128)
cvx_knapsack_kernel(const float* __restrict__ costs,
                    const float* __restrict__ wg,
                    float* __restrict__ out) {
    int tid = blockIdx.x * blockDim.x + threadIdx.x;
    int row = tid >> 3;
    int q   = tid & 7;
    if (row >= BROWS) return;

    float2 w[NPAIR], ec[NPAIR], x[NPAIR];

    const float4* wp = reinterpret_cast<const float4*>(wg + q * IPT);
#pragma unroll
    for (int j = 0; j < NPAIR / 2; j++) {
        float4 wv = wp[j];
        w[2*j]     = make_float2(wv.x, wv.y);
        w[2*j + 1] = make_float2(wv.z, wv.w);
    }

    const float4* cp = reinterpret_cast<const float4*>(costs + row * NITEMS + q * IPT);
#pragma unroll
    for (int j = 0; j < NPAIR / 2; j++) {
        float4 cv = cp[j];
        x[2*j].x   = __saturatef(cv.x);         // clip(c, 0, 1)
        x[2*j].y   = __saturatef(cv.y);
        x[2*j+1].x = __saturatef(cv.z);
        x[2*j+1].y = __saturatef(cv.w);
        ec[2*j]   = make_float2(ETAC * cv.x, ETAC * cv.y);
        ec[2*j+1] = make_float2(ETAC * cv.z, ETAC * cv.w);
    }

    // Scalar secant state (uniform across the row's 8 lanes).
    float lam = 0.f, rd = 1.0f / 1000.0f;       // ~1/Sum_interior w^2
    float lamp = 0.f, fp = 0.f;
    float na;

    // Cold projection: NIT0 bracketed secant iterations.
    {
        float lo = 0.f, hi = HI0;
#pragma unroll 1
        for (int it = 0; it < NIT0; it++) {
            float f = evalg(x, w, lam);
            bool over = f > 0.f;
            lo = over ? lam : lo;
            hi = over ? hi  : lam;
            if (it > 0) {
                float rds = __fdividef(lam - lamp, fp - f);
                rd = (rds > 0.f && rds < 1e12f) ? rds : rd;
            }
            lamp = lam;
            fp   = f;
            float ln = fmaf(f, rd, lam);
            ln = fmaxf(ln, lo);                 // NaN-safe clamps
            ln = fminf(ln, hi);
            lam = ln;
        }
        na = applyp(x, w, lam);
    }

    // 120 PGD steps: x = project(k*x + eta*c), k = 1 - eta/||x||  (MU = 1)
#pragma unroll 1
    for (int t = 0; t < NPGD; t++) {
        float ss  = red8(na);
        float inv = rsqrtf(ss + 1e-12f);
        float k   = fmaf(-ETAC, inv, 1.0f);
        float2 kk = make_float2(k, k);
#pragma unroll
        for (int j = 0; j < NPAIR; j++)
            x[j] = fma2(kk, x[j], ec[j]);

        // Warm projection: NIT=2 bracketed secant iterations (same-g secant).
        float lo = 0.f, hi = HI0;
#pragma unroll
        for (int it = 0; it < NIT; it++) {
            float f = evalg(x, w, lam);
            bool over = f > 0.f;
            lo = over ? lam : lo;
            hi = over ? hi  : lam;
            if (it > 0) {   // within-projection secant (same g!)
                float rds = __fdividef(lam - lamp, fp - f);
                rd = (rds > 0.f && rds < 1e12f) ? rds : rd;
            }
            lamp = lam;
            fp   = f;
            float ln = fmaf(f, rd, lam);
            ln = fmaxf(ln, lo);
            ln = fminf(ln, hi);
            lam = ln;
        }
        na = applyp(x, w, lam);
    }

    float4* op = reinterpret_cast<float4*>(out + row * NITEMS + q * IPT);
#pragma unroll
    for (int j = 0; j < NPAIR / 2; j++) {
        float4 v;
        v.x = x[2*j].x;     v.y = x[2*j].y;
        v.z = x[2*j + 1].x; v.w = x[2*j + 1].y;
        op[j] = v;
    }
}

extern "C" void kernel_launch(void* const* d_in, const int* in_sizes, int n_in,
                              void* d_out, int out_size) {
    const float* costs = (const float*)d_in[0];
    const float* wts   = (const float*)d_in[1];
    if (n_in >= 2 && in_sizes[0] == NITEMS) {   // guard against input order swap
        costs = (const float*)d_in[1];
        wts   = (const float*)d_in[0];
    }
    float* out = (float*)d_out;

    const int threads = 128;
    const int total   = BROWS * TPR;                       // 131072 threads
    const int blocks  = (total + threads - 1) / threads;   // 1024 blocks
    cvx_knapsack_kernel<<<blocks, threads>>>(costs, wts, out);
}

// round 11
// speedup vs baseline: 1.1138x; 1.1138x over previous
#include <cuda_runtime.h>

// cvx_knapsack_solver: batched PGD + knapsack projection.
// Projection: warm-started SINGLE-EVAL Newton on the piecewise-linear g —
// each eval returns f = g(lam)-CAP and the exact derivative d = sum_int w^2
// of the CURRENT g (valid slope, unlike cross-projection secants).
// Bracketed + NaN/inf-safe; lo=0 clamp subsumes the lam=0 feasibility branch.
// Layout: 8 lanes/row, 8 items/lane, 1 row/thread (4096 warps).

#define BROWS   16384
#define NITEMS  64
#define TPR     8
#define IPT     8
#define NPAIR   4          // IPT/2 float2 pairs
#define CAPC    102.0f
#define NPGD    120
#define ETAC    0.1f
#define NIT0    6          // Newton evals, cold first projection
#define HI0     2.0f       // g(HI0)=0 guaranteed: y <= ~1.6, w >= 1

// Packed dual-fp32 FMA (Blackwell FFMA2). mov.b64 is register pairing only.
__device__ __forceinline__ float2 fma2(float2 a, float2 b, float2 c) {
    float2 r;
    asm("{\n\t"
        ".reg .b64 ra, rb, rc, rd;\n\t"
        "mov.b64 ra, {%2, %3};\n\t"
        "mov.b64 rb, {%4, %5};\n\t"
        "mov.b64 rc, {%6, %7};\n\t"
        "fma.rn.f32x2 rd, ra, rb, rc;\n\t"
        "mov.b64 {%0, %1}, rd;\n\t"
        "}"
        : "=f"(r.x), "=f"(r.y)
        : "f"(a.x), "f"(a.y), "f"(b.x), "f"(b.y), "f"(c.x), "f"(c.y));
    return r;
}

__device__ __forceinline__ float2 clip01(float2 z) {
    z.x = fminf(fmaxf(z.x, 0.f), 1.f);
    z.y = fminf(fmaxf(z.y, 0.f), 1.f);
    return z;
}

// 1.0f if a==b else 0.0f (single FSET; proven in R4).
__device__ __forceinline__ float seteqf(float a, float b) {
    float r;
    asm("set.eq.f32.f32 %0, %1, %2;" : "=f"(r) : "f"(a), "f"(b));
    return r;
}

// Sum over the row's 8-lane group; result valid in ALL 8 lanes.
__device__ __forceinline__ float red8(float v) {
    v += __shfl_xor_sync(0xffffffffu, v, 1);
    v += __shfl_xor_sync(0xffffffffu, v, 2);
    v += __shfl_xor_sync(0xffffffffu, v, 4);
    return v;
}

// One Newton eval: f = g(lam)-CAP, d = sum_{interior} w^2 (exact current-g
// slope magnitude). The two reduction trees are independent and overlap.
__device__ __forceinline__ void evalgd(const float2 x[NPAIR],
                                       const float2 w[NPAIR],
                                       const float2 w2[NPAIR],
                                       float lam, float& f, float& d) {
    float2 m  = make_float2(-lam, -lam);
    float2 s  = make_float2(0.f, 0.f);
    float2 dv = make_float2(0.f, 0.f);
#pragma unroll
    for (int j = 0; j < NPAIR; j++) {
        float2 z = fma2(m, w[j], x[j]);
        float2 h = clip01(z);
        s = fma2(h, w[j], s);
        float2 ind;
        ind.x = seteqf(h.x, z.x);       // interior <=> unclipped
        ind.y = seteqf(h.y, z.y);
        dv = fma2(ind, w2[j], dv);
    }
    f = red8(s.x + s.y) - CAPC;
    d = red8(dv.x + dv.y);
}

// x = clip(x - lam*w, 0, 1); return this lane's ||x||^2 partial.
__device__ __forceinline__ float applyp(float2 x[NPAIR],
                                        const float2 w[NPAIR], float lam) {
    float2 m  = make_float2(-lam, -lam);
    float2 aa = make_float2(0.f, 0.f);
    float2 ab = make_float2(0.f, 0.f);
#pragma unroll
    for (int j = 0; j < NPAIR; j += 2) {
        x[j]     = clip01(fma2(m, w[j],     x[j]));
        x[j + 1] = clip01(fma2(m, w[j + 1], x[j + 1]));
        aa = fma2(x[j],     x[j],     aa);
        ab = fma2(x[j + 1], x[j + 1], ab);
    }
    return aa.x + aa.y + ab.x + ab.y;
}

__global__ void __launch_bounds__(128)
cvx_knapsack_kernel(const float* __restrict__ costs,
                    const float* __restrict__ wg,
                    float* __restrict__ out) {
    int tid = blockIdx.x * blockDim.x + threadIdx.x;
    int row = tid >> 3;
    int q   = tid & 7;
    if (row >= BROWS) return;

    float2 w[NPAIR], w2[NPAIR], ec[NPAIR], x[NPAIR];

    const float4* wp = reinterpret_cast<const float4*>(wg + q * IPT);
#pragma unroll
    for (int j = 0; j < NPAIR / 2; j++) {
        float4 wv = wp[j];
        w[2*j]     = make_float2(wv.x, wv.y);
        w[2*j + 1] = make_float2(wv.z, wv.w);
    }
#pragma unroll
    for (int j = 0; j < NPAIR; j++)
        w2[j] = make_float2(w[j].x * w[j].x, w[j].y * w[j].y);

    const float4* cp = reinterpret_cast<const float4*>(costs + row * NITEMS + q * IPT);
#pragma unroll
    for (int j = 0; j < NPAIR / 2; j++) {
        float4 cv = cp[j];
        x[2*j].x   = __saturatef(cv.x);         // clip(c, 0, 1)
        x[2*j].y   = __saturatef(cv.y);
        x[2*j+1].x = __saturatef(cv.z);
        x[2*j+1].y = __saturatef(cv.w);
        ec[2*j]   = make_float2(ETAC * cv.x, ETAC * cv.y);
        ec[2*j+1] = make_float2(ETAC * cv.z, ETAC * cv.w);
    }

    float lam = 0.f;
    float na;

    // Cold projection: NIT0 bracketed Newton iterations.
    {
        float lo = 0.f, hi = HI0;
#pragma unroll 1
        for (int it = 0; it < NIT0; it++) {
            float f, d;
            evalgd(x, w, w2, lam, f, d);
            bool over = f > 0.f;
            lo = over ? lam : lo;
            hi = over ? hi  : lam;
            float ln = lam + __fdividef(f, d);
            ln = fmaxf(ln, lo);                 // NaN/inf-safe clamps
            ln = fminf(ln, hi);
            lam = ln;
        }
        na = applyp(x, w, lam);
    }

    // 120 PGD steps: x = project(k*x + eta*c), k = 1 - eta/||x||  (MU = 1).
    // Each warm projection: ONE Newton eval (exact current-g slope), bracketed.
#pragma unroll 1
    for (int t = 0; t < NPGD; t++) {
        float ss  = red8(na);
        float inv = rsqrtf(ss + 1e-12f);
        float k   = fmaf(-ETAC, inv, 1.0f);
        float2 kk = make_float2(k, k);
#pragma unroll
        for (int j = 0; j < NPAIR; j++)
            x[j] = fma2(kk, x[j], ec[j]);

        float f, d;
        evalgd(x, w, w2, lam, f, d);
        bool over = f > 0.f;
        float lo = over ? lam : 0.f;
        float hi = over ? HI0 : lam;
        float ln = lam + __fdividef(f, d);
        ln = fmaxf(ln, lo);                     // NaN/inf-safe clamps
        ln = fminf(ln, hi);
        lam = ln;

        na = applyp(x, w, lam);
    }

    float4* op = reinterpret_cast<float4*>(out + row * NITEMS + q * IPT);
#pragma unroll
    for (int j = 0; j < NPAIR / 2; j++) {
        float4 v;
        v.x = x[2*j].x;     v.y = x[2*j].y;
        v.z = x[2*j + 1].x; v.w = x[2*j + 1].y;
        op[j] = v;
    }
}

extern "C" void kernel_launch(void* const* d_in, const int* in_sizes, int n_in,
                              void* d_out, int out_size) {
    const float* costs = (const float*)d_in[0];
    const float* wts   = (const float*)d_in[1];
    if (n_in >= 2 && in_sizes[0] == NITEMS) {   // guard against input order swap
        costs = (const float*)d_in[1];
        wts   = (const float*)d_in[0];
    }
    float* out = (float*)d_out;

    const int threads = 128;
    const int total   = BROWS * TPR;                       // 131072 threads
    const int blocks  = (total + threads - 1) / threads;   // 1024 blocks
    cvx_knapsack_kernel<<<blocks, threads>>>(costs, wts, out);
}

// round 12
// speedup vs baseline: 1.2149x; 1.0907x over previous
#include <cuda_runtime.h>

// cvx_knapsack_solver: batched PGD + knapsack projection.
// Projection: warm-started single-eval Newton on piecewise-linear g (f and the
// exact current-g derivative d from one pass), bracketed + NaN/inf-safe.
// R12: apply loop uses scalar fma.rn.sat.f32 (fused clip); f/d reduced with a
// 4-SHFL split-exchange tree; 64-thread blocks for placement granularity.
// Layout: 8 lanes/row, 8 items/lane, 1 row/thread (4096 warps).

#define BROWS   16384
#define NITEMS  64
#define TPR     8
#define IPT     8
#define NPAIR   4          // IPT/2 float2 pairs
#define CAPC    102.0f
#define NPGD    120
#define ETAC    0.1f
#define NIT0    6          // Newton evals, cold first projection
#define HI0     2.0f       // g(HI0)=0 guaranteed: y <= ~1.6, w >= 1

// Packed dual-fp32 FMA (Blackwell FFMA2). mov.b64 is register pairing only.
__device__ __forceinline__ float2 fma2(float2 a, float2 b, float2 c) {
    float2 r;
    asm("{\n\t"
        ".reg .b64 ra, rb, rc, rd;\n\t"
        "mov.b64 ra, {%2, %3};\n\t"
        "mov.b64 rb, {%4, %5};\n\t"
        "mov.b64 rc, {%6, %7};\n\t"
        "fma.rn.f32x2 rd, ra, rb, rc;\n\t"
        "mov.b64 {%0, %1}, rd;\n\t"
        "}"
        : "=f"(r.x), "=f"(r.y)
        : "f"(a.x), "f"(a.y), "f"(b.x), "f"(b.y), "f"(c.x), "f"(c.y));
    return r;
}

// Scalar saturating FMA: clip(a*b+c, 0, 1) in one instruction (legal PTX).
__device__ __forceinline__ float fmasat(float a, float b, float c) {
    float r;
    asm("fma.rn.sat.f32 %0, %1, %2, %3;" : "=f"(r) : "f"(a), "f"(b), "f"(c));
    return r;
}

__device__ __forceinline__ float2 clip01(float2 z) {
    z.x = fminf(fmaxf(z.x, 0.f), 1.f);
    z.y = fminf(fmaxf(z.y, 0.f), 1.f);
    return z;
}

// 1.0f if a==b else 0.0f (single FSET; proven in R4).
__device__ __forceinline__ float seteqf(float a, float b) {
    float r;
    asm("set.eq.f32.f32 %0, %1, %2;" : "=f"(r) : "f"(a), "f"(b));
    return r;
}

// Sum over the row's 8-lane group; result valid in ALL 8 lanes.
__device__ __forceinline__ float red8(float v) {
    v += __shfl_xor_sync(0xffffffffu, v, 1);
    v += __shfl_xor_sync(0xffffffffu, v, 2);
    v += __shfl_xor_sync(0xffffffffu, v, 4);
    return v;
}

// Split-exchange reduction: lanes 0-3 of the group reduce fpart, lanes 4-7
// reduce dpart; a final xor-4 gives every lane both totals. 4 SHFL (vs 6).
__device__ __forceinline__ void red8_fd(float fpart, float dpart, bool hb,
                                        float& F, float& D) {
    float v = hb ? fpart : dpart;                   // send the one I don't reduce
    float u = __shfl_xor_sync(0xffffffffu, v, 4);
    float t = (hb ? dpart : fpart) + u;             // my quantity, both halves
    t += __shfl_xor_sync(0xffffffffu, t, 1);
    t += __shfl_xor_sync(0xffffffffu, t, 2);
    float o = __shfl_xor_sync(0xffffffffu, t, 4);   // partner half's total
    F = hb ? o : t;
    D = hb ? t : o;
}

// One Newton eval: f = g(lam)-CAP, d = sum_{interior} w^2 (exact current-g
// slope magnitude). Partials reduced with the 4-SHFL split tree.
__device__ __forceinline__ void evalgd(const float2 x[NPAIR],
                                       const float2 w[NPAIR],
                                       const float2 w2[NPAIR],
                                       float lam, bool hb, float& f, float& d) {
    float2 m  = make_float2(-lam, -lam);
    float2 s  = make_float2(0.f, 0.f);
    float2 dv = make_float2(0.f, 0.f);
#pragma unroll
    for (int j = 0; j < NPAIR; j++) {
        float2 z = fma2(m, w[j], x[j]);
        float2 h = clip01(z);
        s = fma2(h, w[j], s);
        float2 ind;
        ind.x = seteqf(h.x, z.x);       // interior <=> unclipped
        ind.y = seteqf(h.y, z.y);
        dv = fma2(ind, w2[j], dv);
    }
    float F, D;
    red8_fd(s.x + s.y, dv.x + dv.y, hb, F, D);
    f = F - CAPC;
    d = D;
}

// x = clip(x - lam*w, 0, 1) via saturating scalar FMA (1 instr/item);
// returns this lane's ||x||^2 partial (scalar accumulators, no pairing).
__device__ __forceinline__ float applyp(float2 x[NPAIR],
                                        const float2 w[NPAIR], float lam) {
    float nl = -lam;
    float a0 = 0.f, a1 = 0.f;
#pragma unroll
    for (int j = 0; j < NPAIR; j++) {
        float hx = fmasat(nl, w[j].x, x[j].x);
        float hy = fmasat(nl, w[j].y, x[j].y);
        x[j].x = hx;
        x[j].y = hy;
        a0 = fmaf(hx, hx, a0);
        a1 = fmaf(hy, hy, a1);
    }
    return a0 + a1;
}

__global__ void __launch_bounds__(64)
cvx_knapsack_kernel(const float* __restrict__ costs,
                    const float* __restrict__ wg,
                    float* __restrict__ out) {
    int tid = blockIdx.x * blockDim.x + threadIdx.x;
    int row = tid >> 3;
    int q   = tid & 7;
    if (row >= BROWS) return;
    bool hb = (q & 4) != 0;

    float2 w[NPAIR], w2[NPAIR], ec[NPAIR], x[NPAIR];

    const float4* wp = reinterpret_cast<const float4*>(wg + q * IPT);
#pragma unroll
    for (int j = 0; j < NPAIR / 2; j++) {
        float4 wv = wp[j];
        w[2*j]     = make_float2(wv.x, wv.y);
        w[2*j + 1] = make_float2(wv.z, wv.w);
    }
#pragma unroll
    for (int j = 0; j < NPAIR; j++)
        w2[j] = make_float2(w[j].x * w[j].x, w[j].y * w[j].y);

    const float4* cp = reinterpret_cast<const float4*>(costs + row * NITEMS + q * IPT);
#pragma unroll
    for (int j = 0; j < NPAIR / 2; j++) {
        float4 cv = cp[j];
        x[2*j].x   = __saturatef(cv.x);         // clip(c, 0, 1)
        x[2*j].y   = __saturatef(cv.y);
        x[2*j+1].x = __saturatef(cv.z);
        x[2*j+1].y = __saturatef(cv.w);
        ec[2*j]   = make_float2(ETAC * cv.x, ETAC * cv.y);
        ec[2*j+1] = make_float2(ETAC * cv.z, ETAC * cv.w);
    }

    float lam = 0.f;
    float na;

    // Cold projection: NIT0 bracketed Newton iterations.
    {
        float lo = 0.f, hi = HI0;
#pragma unroll 1
        for (int it = 0; it < NIT0; it++) {
            float f, d;
            evalgd(x, w, w2, lam, hb, f, d);
            bool over = f > 0.f;
            lo = over ? lam : lo;
            hi = over ? hi  : lam;
            float ln = lam + __fdividef(f, d);
            ln = fmaxf(ln, lo);                 // NaN/inf-safe clamps
            ln = fminf(ln, hi);
            lam = ln;
        }
        na = applyp(x, w, lam);
    }

    // 120 PGD steps: x = project(k*x + eta*c), k = 1 - eta/||x||  (MU = 1).
    // Warm projection: ONE Newton eval (exact current-g slope), bracketed.
#pragma unroll 1
    for (int t = 0; t < NPGD; t++) {
        float ss  = red8(na);
        float inv = rsqrtf(ss + 1e-12f);
        float k   = fmaf(-ETAC, inv, 1.0f);
        float2 kk = make_float2(k, k);
#pragma unroll
        for (int j = 0; j < NPAIR; j++)
            x[j] = fma2(kk, x[j], ec[j]);

        float f, d;
        evalgd(x, w, w2, lam, hb, f, d);
        bool over = f > 0.f;
        float lo = over ? lam : 0.f;
        float hi = over ? HI0 : lam;
        float ln = lam + __fdividef(f, d);
        ln = fmaxf(ln, lo);                     // NaN/inf-safe clamps
        ln = fminf(ln, hi);
        lam = ln;

        na = applyp(x, w, lam);
    }

    float4* op = reinterpret_cast<float4*>(out + row * NITEMS + q * IPT);
#pragma unroll
    for (int j = 0; j < NPAIR / 2; j++) {
        float4 v;
        v.x = x[2*j].x;     v.y = x[2*j].y;
        v.z = x[2*j + 1].x; v.w = x[2*j + 1].y;
        op[j] = v;
    }
}

extern "C" void kernel_launch(void* const* d_in, const int* in_sizes, int n_in,
                              void* d_out, int out_size) {
    const float* costs = (const float*)d_in[0];
    const float* wts   = (const float*)d_in[1];
    if (n_in >= 2 && in_sizes[0] == NITEMS) {   // guard against input order swap
        costs = (const float*)d_in[1];
        wts   = (const float*)d_in[0];
    }
    float* out = (float*)d_out;

    const int threads = 64;
    const int total   = BROWS * TPR;                       // 131072 threads
    const int blocks  = (total + threads - 1) / threads;   // 2048 blocks
    cvx_knapsack_kernel<<<blocks, threads>>>(costs, wts, out);
}

// round 13
// speedup vs baseline: 1.2926x; 1.0640x over previous
#include <cuda_runtime.h>

// cvx_knapsack_solver: batched PGD + knapsack projection.
// Projection: warm-started single-eval Newton on piecewise-linear g (f and
// exact current-g derivative d in one pass), bracketed + NaN/inf-safe.
// R13: the eval pass also produces the ||x||^2 used for the NEXT step's
// gradient scale (h at the pre-Newton lam ~ applied x to O(dlam)); its 3-SHFL
// tree overlaps the 4-SHFL f/d split tree, and apply is 8 bare sat-FMAs.
// Layout: 8 lanes/row, 8 items/lane, 1 row/thread (4096 warps).

#define BROWS   16384
#define NITEMS  64
#define TPR     8
#define IPT     8
#define NPAIR   4          // IPT/2 float2 pairs
#define CAPC    102.0f
#define NPGD    120
#define ETAC    0.1f
#define NIT0    6          // Newton evals, cold first projection
#define HI0     2.0f       // g(HI0)=0 guaranteed: y <= ~1.6, w >= 1

// Packed dual-fp32 FMA (Blackwell FFMA2). mov.b64 is register pairing only.
__device__ __forceinline__ float2 fma2(float2 a, float2 b, float2 c) {
    float2 r;
    asm("{\n\t"
        ".reg .b64 ra, rb, rc, rd;\n\t"
        "mov.b64 ra, {%2, %3};\n\t"
        "mov.b64 rb, {%4, %5};\n\t"
        "mov.b64 rc, {%6, %7};\n\t"
        "fma.rn.f32x2 rd, ra, rb, rc;\n\t"
        "mov.b64 {%0, %1}, rd;\n\t"
        "}"
        : "=f"(r.x), "=f"(r.y)
        : "f"(a.x), "f"(a.y), "f"(b.x), "f"(b.y), "f"(c.x), "f"(c.y));
    return r;
}

// Scalar saturating FMA: clip(a*b+c, 0, 1) in one instruction.
__device__ __forceinline__ float fmasat(float a, float b, float c) {
    float r;
    asm("fma.rn.sat.f32 %0, %1, %2, %3;" : "=f"(r) : "f"(a), "f"(b), "f"(c));
    return r;
}

// 1.0f if a==b else 0.0f (single FSET).
__device__ __forceinline__ float seteqf(float a, float b) {
    float r;
    asm("set.eq.f32.f32 %0, %1, %2;" : "=f"(r) : "f"(a), "f"(b));
    return r;
}

// Sum over the row's 8-lane group; result valid in ALL 8 lanes.
__device__ __forceinline__ float red8(float v) {
    v += __shfl_xor_sync(0xffffffffu, v, 1);
    v += __shfl_xor_sync(0xffffffffu, v, 2);
    v += __shfl_xor_sync(0xffffffffu, v, 4);
    return v;
}

// Split-exchange reduction: half the lanes reduce fpart, the others dpart;
// final xor-4 gives every lane both totals. 4 SHFL for two quantities.
__device__ __forceinline__ void red8_fd(float fpart, float dpart, bool hb,
                                        float& F, float& D) {
    float v = hb ? fpart : dpart;
    float u = __shfl_xor_sync(0xffffffffu, v, 4);
    float t = (hb ? dpart : fpart) + u;
    t += __shfl_xor_sync(0xffffffffu, t, 1);
    t += __shfl_xor_sync(0xffffffffu, t, 2);
    float o = __shfl_xor_sync(0xffffffffu, t, 4);
    F = hb ? o : t;
    D = hb ? t : o;
}

// One fused eval: f = g(lam)-CAP, d = sum_{interior} w^2, n = ||h||^2 with
// h = clip(x - lam*w, 0, 1). The f/d split tree and the n tree overlap.
__device__ __forceinline__ void evalgdn(const float2 x[NPAIR],
                                        const float2 w[NPAIR],
                                        const float2 w2[NPAIR],
                                        float lam, bool hb,
                                        float& f, float& d, float& n) {
    float nl = -lam;
    float2 m  = make_float2(nl, nl);
    float2 s  = make_float2(0.f, 0.f);
    float2 dv = make_float2(0.f, 0.f);
    float2 nv = make_float2(0.f, 0.f);
#pragma unroll
    for (int j = 0; j < NPAIR; j++) {
        float2 z = fma2(m, w[j], x[j]);
        float2 h;
        h.x = fmasat(nl, w[j].x, x[j].x);
        h.y = fmasat(nl, w[j].y, x[j].y);
        s = fma2(h, w[j], s);
        float2 ind;
        ind.x = seteqf(h.x, z.x);       // interior <=> unclipped
        ind.y = seteqf(h.y, z.y);
        dv = fma2(ind, w2[j], dv);
        nv = fma2(h, h, nv);
    }
    float F, D;
    red8_fd(s.x + s.y, dv.x + dv.y, hb, F, D);
    n = red8(nv.x + nv.y);              // independent tree, overlaps red8_fd
    f = F - CAPC;
    d = D;
}

// x = clip(x - lam*w, 0, 1): 8 bare saturating FMAs.
__device__ __forceinline__ void applyx(float2 x[NPAIR],
                                       const float2 w[NPAIR], float lam) {
    float nl = -lam;
#pragma unroll
    for (int j = 0; j < NPAIR; j++) {
        x[j].x = fmasat(nl, w[j].x, x[j].x);
        x[j].y = fmasat(nl, w[j].y, x[j].y);
    }
}

// Cold-path apply that also returns this lane's exact ||x||^2 partial.
__device__ __forceinline__ float applyp(float2 x[NPAIR],
                                        const float2 w[NPAIR], float lam) {
    float nl = -lam;
    float a0 = 0.f, a1 = 0.f;
#pragma unroll
    for (int j = 0; j < NPAIR; j++) {
        float hx = fmasat(nl, w[j].x, x[j].x);
        float hy = fmasat(nl, w[j].y, x[j].y);
        x[j].x = hx;
        x[j].y = hy;
        a0 = fmaf(hx, hx, a0);
        a1 = fmaf(hy, hy, a1);
    }
    return a0 + a1;
}

__global__ void __launch_bounds__(64)
cvx_knapsack_kernel(const float* __restrict__ costs,
                    const float* __restrict__ wg,
                    float* __restrict__ out) {
    int tid = blockIdx.x * blockDim.x + threadIdx.x;
    int row = tid >> 3;
    int q   = tid & 7;
    if (row >= BROWS) return;
    bool hb = (q & 4) != 0;

    float2 w[NPAIR], w2[NPAIR], ec[NPAIR], x[NPAIR];

    const float4* wp = reinterpret_cast<const float4*>(wg + q * IPT);
#pragma unroll
    for (int j = 0; j < NPAIR / 2; j++) {
        float4 wv = wp[j];
        w[2*j]     = make_float2(wv.x, wv.y);
        w[2*j + 1] = make_float2(wv.z, wv.w);
    }
#pragma unroll
    for (int j = 0; j < NPAIR; j++)
        w2[j] = make_float2(w[j].x * w[j].x, w[j].y * w[j].y);

    const float4* cp = reinterpret_cast<const float4*>(costs + row * NITEMS + q * IPT);
#pragma unroll
    for (int j = 0; j < NPAIR / 2; j++) {
        float4 cv = cp[j];
        x[2*j].x   = __saturatef(cv.x);         // clip(c, 0, 1)
        x[2*j].y   = __saturatef(cv.y);
        x[2*j+1].x = __saturatef(cv.z);
        x[2*j+1].y = __saturatef(cv.w);
        ec[2*j]   = make_float2(ETAC * cv.x, ETAC * cv.y);
        ec[2*j+1] = make_float2(ETAC * cv.z, ETAC * cv.w);
    }

    float lam = 0.f;
    float n;    // ||x||^2 estimate for the next gradient step

    // Cold projection: NIT0 bracketed Newton iterations + exact-norm apply.
    {
        float lo = 0.f, hi = HI0;
#pragma unroll 1
        for (int it = 0; it < NIT0; it++) {
            float f, d, nn;
            evalgdn(x, w, w2, lam, hb, f, d, nn);
            bool over = f > 0.f;
            lo = over ? lam : lo;
            hi = over ? hi  : lam;
            float ln = lam + __fdividef(f, d);
            ln = fmaxf(ln, lo);                 // NaN/inf-safe clamps
            ln = fminf(ln, hi);
            lam = ln;
        }
        n = red8(applyp(x, w, lam));
    }

    // 120 PGD steps: x = project(k*x + eta*c), k = 1 - eta/||x||  (MU = 1).
    // Warm projection: ONE fused Newton eval; the eval's h-norm (pre-Newton
    // lam) serves as the next step's ||x||^2 (error O(dlam), step-size only).
#pragma unroll 1
    for (int t = 0; t < NPGD; t++) {
        float inv = rsqrtf(n + 1e-12f);
        float k   = fmaf(-ETAC, inv, 1.0f);
        float2 kk = make_float2(k, k);
#pragma unroll
        for (int j = 0; j < NPAIR; j++)
            x[j] = fma2(kk, x[j], ec[j]);

        float f, d, nn;
        evalgdn(x, w, w2, lam, hb, f, d, nn);
        bool over = f > 0.f;
        float lo = over ? lam : 0.f;
        float hi = over ? HI0 : lam;
        float ln = lam + __fdividef(f, d);
        ln = fmaxf(ln, lo);                     // NaN/inf-safe clamps
        ln = fminf(ln, hi);
        lam = ln;
        n = nn;

        applyx(x, w, lam);
    }

    float4* op = reinterpret_cast<float4*>(out + row * NITEMS + q * IPT);
#pragma unroll
    for (int j = 0; j < NPAIR / 2; j++) {
        float4 v;
        v.x = x[2*j].x;     v.y = x[2*j].y;
        v.z = x[2*j + 1].x; v.w = x[2*j + 1].y;
        op[j] = v;
    }
}

extern "C" void kernel_launch(void* const* d_in, const int* in_sizes, int n_in,
                              void* d_out, int out_size) {
    const float* costs = (const float*)d_in[0];
    const float* wts   = (const float*)d_in[1];
    if (n_in >= 2 && in_sizes[0] == NITEMS) {   // guard against input order swap
        costs = (const float*)d_in[1];
        wts   = (const float*)d_in[0];
    }
    float* out = (float*)d_out;

    const int threads = 64;
    const int total   = BROWS * TPR;                       // 131072 threads
    const int blocks  = (total + threads - 1) / threads;   // 2048 blocks
    cvx_knapsack_kernel<<<blocks, threads>>>(costs, wts, out);
}